// round 8
// baseline (speedup 1.0000x reference)
#include <cuda_runtime.h>
#include <cuda_bf16.h>
#include <cstdint>

// Problem dims
#define BB   8
#define SS   4096
#define DD   1024
#define HH   16
#define DHH  64
#define TT   (BB*SS)      // 32768 tokens
#define RS   2048         // int8 row stride: [d0 plane | d1 plane]

// ---------------------------------------------------------------------------
// Scratch (static __device__ — no allocations allowed)
// ---------------------------------------------------------------------------
__device__ int8_t g_Xq[(size_t)TT * RS];          // x digits      64 MiB
__device__ int8_t g_Wq[4][(size_t)DD * RS];       // weight digits  8 MiB
__device__ int8_t g_Cq[(size_t)TT * RS];          // ctx digits    64 MiB
__device__ float  g_sX[TT];
__device__ float  g_sW[4][DD];
__device__ float  g_sC[TT];
__device__ float  g_Q [(size_t)TT * DD];
__device__ float  g_K [(size_t)TT * DD];
__device__ float  g_V [(size_t)TT * DD];

// ---------------------------------------------------------------------------
// Fused quantization: one warp per row. Rows [0,TT) = x; [TT, TT+4*DD) = the
// 4 weight matrices. x ~ s*(d0 + d1/254), s = rowmax/127.
// ---------------------------------------------------------------------------
struct QArgs {
    const float* x;
    const float* w[4];
    int8_t* xq; int8_t* wq;      // wq: 4 matrices contiguous, DD*RS each
    float*  sx; float* sw;       // sw: 4*DD
};

__global__ void __launch_bounds__(256) quant_kernel(QArgs qa) {
    const int lane = threadIdx.x & 31;
    const int gw = blockIdx.x * 8 + (threadIdx.x >> 5);

    const float* src; int8_t* dst; float* sout;
    if (gw < TT) {
        src = qa.x + (size_t)gw * DD;
        dst = qa.xq + (size_t)gw * RS;
        sout = qa.sx + gw;
    } else {
        const int w2 = gw - TT, m = w2 >> 10, r = w2 & 1023;
        src = qa.w[m] + (size_t)r * DD;
        dst = qa.wq + ((size_t)m * DD + r) * RS;
        sout = qa.sw + m * DD + r;
    }

    float4 v[8];
    float mx = 0.f;
#pragma unroll
    for (int g = 0; g < 8; g++) {
        v[g] = ((const float4*)src)[g * 32 + lane];
        mx = fmaxf(mx, fmaxf(fmaxf(fabsf(v[g].x), fabsf(v[g].y)),
                             fmaxf(fabsf(v[g].z), fabsf(v[g].w))));
    }
#pragma unroll
    for (int off = 16; off > 0; off >>= 1)
        mx = fmaxf(mx, __shfl_xor_sync(0xffffffffu, mx, off));

    const float s   = (mx > 0.f) ? mx / 127.f : 1.f;
    const float inv = (mx > 0.f) ? 127.f / mx : 0.f;

#pragma unroll
    for (int g = 0; g < 8; g++) {
        float f[4] = {v[g].x, v[g].y, v[g].z, v[g].w};
        uint32_t p0 = 0, p1 = 0;
#pragma unroll
        for (int e = 0; e < 4; e++) {
            int d0 = __float2int_rn(f[e] * inv);
            float r = f[e] - s * (float)d0;
            int d1 = __float2int_rn(r * 254.f * inv);
            d1 = max(-127, min(127, d1));
            p0 |= (uint32_t)(d0 & 0xFF) << (8 * e);
            p1 |= (uint32_t)(d1 & 0xFF) << (8 * e);
        }
        *(uint32_t*)(dst + g * 128 + lane * 4)        = p0;
        *(uint32_t*)(dst + DD + g * 128 + lane * 4)   = p1;
    }
    if (lane == 0) *sout = s;
}

// ---------------------------------------------------------------------------
// int8 NT GEMM (IMMA m16n8k32), 2-digit product form:
//   C = sA[i]*sB[j]*( acc1 + acc2/254 ) + bias
//   acc1 = d0*e0 ; acc2 = d0*e1 + d1*e0
// CTA tile 256x64 (8 warps, warp 64x32), BK=32 bytes, 4-stage cp.async.
// smem rows (48B stride): [0,256) Ad0 | [256,512) Ad1 | [512,576) Bd0 | [576,640) Bd1
// ---------------------------------------------------------------------------
struct GemmArgsQ {
    const int8_t* A;  const float* sA;
    const int8_t* Bm[3]; const float* sB[3];
    const float*  bias[3]; float* C[3];
};

#define BM 256
#define BN 64
#define STG_ROWS 640
#define SROW 48
#define STAGE_B (STG_ROWS * SROW)          // 30720
#define STAGES 4
#define NKT 32
#define SMEM_BYTES (STAGES * STAGE_B)      // 122880
#define INV254 (1.f / 254.f)

__device__ __forceinline__ void imma(int32_t c[4], uint32_t a0, uint32_t a1,
                                     uint32_t a2, uint32_t a3,
                                     uint32_t b0, uint32_t b1) {
    asm volatile(
        "mma.sync.aligned.m16n8k32.row.col.s32.s8.s8.s32 "
        "{%0,%1,%2,%3}, {%4,%5,%6,%7}, {%8,%9}, {%0,%1,%2,%3};\n"
        : "+r"(c[0]), "+r"(c[1]), "+r"(c[2]), "+r"(c[3])
        : "r"(a0), "r"(a1), "r"(a2), "r"(a3), "r"(b0), "r"(b1));
}

__device__ __forceinline__ uint32_t lds32(uint32_t a) {
    uint32_t v;
    asm volatile("ld.shared.b32 %0, [%1];" : "=r"(v) : "r"(a));
    return v;
}

__device__ __forceinline__ void cp16(uint32_t s, const void* g) {
    asm volatile("cp.async.cg.shared.global [%0], [%1], 16;" :: "r"(s), "l"(g));
}

__global__ void __launch_bounds__(256, 1) gemm_q(GemmArgsQ args) {
    extern __shared__ char smem[];
    const uint32_t sbase = (uint32_t)__cvta_generic_to_shared(smem);

    const int z = blockIdx.z;
    const int8_t* __restrict__ A  = args.A;
    const int8_t* __restrict__ Bw = args.Bm[z];
    const float* __restrict__ sA  = args.sA;
    const float* __restrict__ sB  = args.sB[z];
    const float* __restrict__ bias = args.bias[z];
    float* __restrict__ C          = args.C[z];

    const int bn  = blockIdx.x * BN;
    const int bm  = blockIdx.y * BM;
    const int tid = threadIdx.x;
    const int warp = tid >> 5, lane = tid & 31;
    const int wm = (warp >> 1) * 64;     // 0/64/128/192
    const int wn = (warp & 1) * 32;      // 0/32
    const int lr = lane >> 2, lc = (lane & 3) * 4;

    // loader: 1280 16B-chunks per stage, 5 per thread
    auto issue = [&](int kt, int st) {
        const int kc = kt * 32;
        const uint32_t s0 = sbase + st * STAGE_B;
#pragma unroll
        for (int j = 0; j < 5; j++) {
            const int c = tid + 256 * j;          // 0..1279
            const int row = c >> 1, half = (c & 1) * 16;
            const int8_t* g;
            if (row < 256)       g = A  + (size_t)(bm + row) * RS + kc + half;
            else if (row < 512)  g = A  + (size_t)(bm + row - 256) * RS + DD + kc + half;
            else if (row < 576)  g = Bw + (size_t)(bn + row - 512) * RS + kc + half;
            else                 g = Bw + (size_t)(bn + row - 576) * RS + DD + kc + half;
            cp16(s0 + row * SROW + half, g);
        }
        asm volatile("cp.async.commit_group;");
    };

    int32_t acc1[4][4][4], acc2[4][4][4];
#pragma unroll
    for (int i = 0; i < 4; i++)
#pragma unroll
        for (int j = 0; j < 4; j++)
#pragma unroll
            for (int r = 0; r < 4; r++) { acc1[i][j][r] = 0; acc2[i][j][r] = 0; }

    issue(0, 0); issue(1, 1); issue(2, 2);

    for (int kt = 0; kt < NKT; kt++) {
        if (kt + 3 < NKT) { asm volatile("cp.async.wait_group 2;"); }
        else              { asm volatile("cp.async.wait_group 0;"); }
        __syncthreads();
        if (kt + 3 < NKT) issue(kt + 3, (kt + 3) & 3);

        const uint32_t s0 = sbase + (kt & 3) * STAGE_B;

        // B fragments: 4 n-tiles x 2 digits
        uint32_t bd0[4][2], bd1[4][2];
#pragma unroll
        for (int j = 0; j < 4; j++) {
            const uint32_t rb = s0 + (512 + wn + j * 8 + lr) * SROW + lc;
            bd0[j][0] = lds32(rb);              bd0[j][1] = lds32(rb + 16);
            bd1[j][0] = lds32(rb + 64 * SROW);  bd1[j][1] = lds32(rb + 64 * SROW + 16);
        }
#pragma unroll
        for (int i = 0; i < 4; i++) {
            const uint32_t ra = s0 + (wm + i * 16 + lr) * SROW + lc;
            uint32_t a0 = lds32(ra),      a1 = lds32(ra + 8 * SROW);
            uint32_t a2 = lds32(ra + 16), a3 = lds32(ra + 8 * SROW + 16);
#pragma unroll
            for (int j = 0; j < 4; j++)
                imma(acc1[i][j], a0, a1, a2, a3, bd0[j][0], bd0[j][1]);
#pragma unroll
            for (int j = 0; j < 4; j++)
                imma(acc2[i][j], a0, a1, a2, a3, bd1[j][0], bd1[j][1]);
            const uint32_t rl = ra + 256 * SROW;
            a0 = lds32(rl);      a1 = lds32(rl + 8 * SROW);
            a2 = lds32(rl + 16); a3 = lds32(rl + 8 * SROW + 16);
#pragma unroll
            for (int j = 0; j < 4; j++)
                imma(acc2[i][j], a0, a1, a2, a3, bd0[j][0], bd0[j][1]);
        }
    }

    // epilogue
    const int qr = lane >> 2, qc = lane & 3;
#pragma unroll
    for (int i = 0; i < 4; i++) {
        const int row0 = bm + wm + i * 16 + qr;
        const float sa0 = sA[row0], sa1 = sA[row0 + 8];
#pragma unroll
        for (int j = 0; j < 4; j++) {
            const int col = bn + wn + j * 8 + qc * 2;
            const float sb0 = sB[col], sb1 = sB[col + 1];
            const float b0 = bias[col], b1 = bias[col + 1];
            float2 v0, v1;
            v0.x = ((float)acc1[i][j][0] + (float)acc2[i][j][0] * INV254) * sa0 * sb0 + b0;
            v0.y = ((float)acc1[i][j][1] + (float)acc2[i][j][1] * INV254) * sa0 * sb1 + b1;
            v1.x = ((float)acc1[i][j][2] + (float)acc2[i][j][2] * INV254) * sa1 * sb0 + b0;
            v1.y = ((float)acc1[i][j][3] + (float)acc2[i][j][3] * INV254) * sa1 * sb1 + b1;
            *(float2*)&C[(size_t)row0 * DD + col]       = v0;
            *(float2*)&C[(size_t)(row0 + 8) * DD + col] = v1;
        }
    }
}

// ---------------------------------------------------------------------------
// Per-token attention over the HEAD axis. One warp per token. Emits ctx
// quantized to int8 digits + per-token scale.
// ---------------------------------------------------------------------------
__global__ void __launch_bounds__(64) attn_kernel(
    const float* __restrict__ Q, const float* __restrict__ K,
    const float* __restrict__ V, int8_t* __restrict__ Cq,
    float* __restrict__ sC) {
    __shared__ float sQ[2][DD], sK[2][DD], sV[2][DD];
    __shared__ float sS[2][HH][HH];

    const int warp = threadIdx.x >> 5, lane = threadIdx.x & 31;
    const size_t t = (size_t)blockIdx.x * 2 + warp;

    const float4* q4 = (const float4*)(Q + t * DD);
    const float4* k4 = (const float4*)(K + t * DD);
    const float4* v4 = (const float4*)(V + t * DD);
#pragma unroll
    for (int i = lane; i < DD / 4; i += 32) {
        ((float4*)sQ[warp])[i] = q4[i];
        ((float4*)sK[warp])[i] = k4[i];
        ((float4*)sV[warp])[i] = v4[i];
    }
    __syncwarp();

    for (int p = lane; p < HH * HH; p += 32) {
        const int h = p >> 4, g = p & 15;
        const float* q = &sQ[warp][h * DHH];
        const float* k = &sK[warp][g * DHH];
        float s = 0.f;
#pragma unroll
        for (int d = 0; d < DHH; d++) s += q[d] * k[d];
        sS[warp][h][g] = s * 0.125f;   // 1/sqrt(64)
    }
    __syncwarp();

    if (lane < HH) {
        float mx = -1e30f;
#pragma unroll
        for (int g = 0; g < HH; g++) mx = fmaxf(mx, sS[warp][lane][g]);
        float sum = 0.f;
#pragma unroll
        for (int g = 0; g < HH; g++) {
            float e = expf(sS[warp][lane][g] - mx);
            sS[warp][lane][g] = e;
            sum += e;
        }
        const float inv = 1.f / sum;
#pragma unroll
        for (int g = 0; g < HH; g++) sS[warp][lane][g] *= inv;
    }
    __syncwarp();

    // ctx values (32 per lane) + row max
    float cv[32];
    float mx = 0.f;
#pragma unroll
    for (int gi = 0; gi < 32; gi++) {
        const int o = lane + 32 * gi;
        const int h = o >> 6, d = o & 63;
        float c = 0.f;
#pragma unroll
        for (int g = 0; g < HH; g++) c += sS[warp][h][g] * sV[warp][g * DHH + d];
        cv[gi] = c;
        mx = fmaxf(mx, fabsf(c));
    }
#pragma unroll
    for (int off = 16; off > 0; off >>= 1)
        mx = fmaxf(mx, __shfl_xor_sync(0xffffffffu, mx, off));

    const float s   = (mx > 0.f) ? mx / 127.f : 1.f;
    const float inv = (mx > 0.f) ? 127.f / mx : 0.f;
    int8_t* out = Cq + t * RS;
#pragma unroll
    for (int gi = 0; gi < 32; gi++) {
        const int o = lane + 32 * gi;
        int d0 = __float2int_rn(cv[gi] * inv);
        float r = cv[gi] - s * (float)d0;
        int d1 = __float2int_rn(r * 254.f * inv);
        d1 = max(-127, min(127, d1));
        out[o]      = (int8_t)d0;
        out[DD + o] = (int8_t)d1;
    }
    if (lane == 0) sC[t] = s;
}

// ---------------------------------------------------------------------------
// Launch (4 launches per call: quant, gemm_qkv, attn, gemm_o)
// ---------------------------------------------------------------------------
extern "C" void kernel_launch(void* const* d_in, const int* in_sizes, int n_in,
                              void* d_out, int out_size) {
    (void)in_sizes; (void)n_in; (void)out_size;
    const float* x  = (const float*)d_in[0];
    const float* wq = (const float*)d_in[1];
    const float* bq = (const float*)d_in[2];
    const float* wk = (const float*)d_in[3];
    const float* bk = (const float*)d_in[4];
    const float* wv = (const float*)d_in[5];
    const float* bv = (const float*)d_in[6];
    const float* wo = (const float*)d_in[7];
    const float* bo = (const float*)d_in[8];
    float* out = (float*)d_out;

    int8_t *Xq, *Wq, *Cq;
    float *sX, *sW, *sC, *Q, *K, *V;
    cudaGetSymbolAddress((void**)&Xq, g_Xq);
    cudaGetSymbolAddress((void**)&Wq, g_Wq);
    cudaGetSymbolAddress((void**)&Cq, g_Cq);
    cudaGetSymbolAddress((void**)&sX, g_sX);
    cudaGetSymbolAddress((void**)&sW, g_sW);
    cudaGetSymbolAddress((void**)&sC, g_sC);
    cudaGetSymbolAddress((void**)&Q,  g_Q);
    cudaGetSymbolAddress((void**)&K,  g_K);
    cudaGetSymbolAddress((void**)&V,  g_V);
    const size_t WQS = (size_t)DD * RS;

    cudaFuncSetAttribute(gemm_q,
                         cudaFuncAttributeMaxDynamicSharedMemorySize, SMEM_BYTES);

    // 1) fused quantization (x + 4 weights)
    QArgs qa;
    qa.x = x; qa.w[0] = wq; qa.w[1] = wk; qa.w[2] = wv; qa.w[3] = wo;
    qa.xq = Xq; qa.wq = Wq; qa.sx = sX; qa.sw = sW;
    quant_kernel<<<(TT + 4 * DD) / 8, 256>>>(qa);

    // 2) fused QKV GEMMs
    GemmArgsQ ga;
    ga.A = Xq; ga.sA = sX;
    ga.Bm[0] = Wq + 0 * WQS; ga.Bm[1] = Wq + 1 * WQS; ga.Bm[2] = Wq + 2 * WQS;
    ga.sB[0] = sW + 0 * DD;  ga.sB[1] = sW + 1 * DD;  ga.sB[2] = sW + 2 * DD;
    ga.bias[0] = bq; ga.bias[1] = bk; ga.bias[2] = bv;
    ga.C[0] = Q; ga.C[1] = K; ga.C[2] = V;
    gemm_q<<<dim3(DD / BN, TT / BM, 3), 256, SMEM_BYTES>>>(ga);

    // 3) per-token head-axis attention -> quantized ctx
    attn_kernel<<<TT / 2, 64>>>(Q, K, V, Cq, sC);

    // 4) output projection
    GemmArgsQ go;
    go.A = Cq; go.sA = sC;
    go.Bm[0] = Wq + 3 * WQS; go.Bm[1] = go.Bm[0]; go.Bm[2] = go.Bm[0];
    go.sB[0] = sW + 3 * DD;  go.sB[1] = go.sB[0]; go.sB[2] = go.sB[0];
    go.bias[0] = bo; go.bias[1] = bo; go.bias[2] = bo;
    go.C[0] = out; go.C[1] = out; go.C[2] = out;
    gemm_q<<<dim3(DD / BN, TT / BM, 1), 256, SMEM_BYTES>>>(go);
}

// round 9
// speedup vs baseline: 5.3433x; 5.3433x over previous
#include <cuda_runtime.h>
#include <cuda_fp16.h>
#include <cstdint>

// Problem dims
#define BB   8
#define SS   4096
#define DD   1024
#define HH   16
#define DHH  64
#define TT   (BB*SS)      // 32768 tokens

// ---------------------------------------------------------------------------
// Scratch (static __device__ — no allocations allowed)
// ---------------------------------------------------------------------------
__device__ __half g_Xh[(size_t)TT * DD];          // x fp16        64 MiB
__device__ __half g_Wh[4][(size_t)DD * DD];       // weights fp16   8 MiB
__device__ float  g_Q [(size_t)TT * DD];
__device__ float  g_K [(size_t)TT * DD];
__device__ float  g_V [(size_t)TT * DD];
__device__ __half g_Ch[(size_t)TT * DD];          // ctx fp16      64 MiB

// ---------------------------------------------------------------------------
// fp32 -> fp16 convert (one thread per float4)
// ---------------------------------------------------------------------------
__global__ void cvt_kernel(const float* __restrict__ src,
                           __half* __restrict__ dst) {
    size_t i = (size_t)blockIdx.x * blockDim.x + threadIdx.x;
    float4 v = ((const float4*)src)[i];
    __half2 h0 = __floats2half2_rn(v.x, v.y);
    __half2 h1 = __floats2half2_rn(v.z, v.w);
    ((__half2*)dst)[i * 2]     = h0;
    ((__half2*)dst)[i * 2 + 1] = h1;
}

// ---------------------------------------------------------------------------
// fp16 NT GEMM:  C[M,N] = A[M,K]*B[N,K]^T + bias, fp32 accumulate.
// CTA tile 256x128 (8 warps, warp 64x64), BK=32, 4-stage cp.async pipeline,
// ldmatrix feeds, stride-40 smem padding. blockIdx.z selects q/k/v.
// ---------------------------------------------------------------------------
struct GemmArgs {
    const __half* A;
    const __half* Bm[3];
    const float*  bias[3];
    float*        C[3];
};

#define BM 256
#define BN 128
#define BK 32
#define SST 40                        // smem row stride (halfs)
#define STAGES 4
#define NKT 32                        // K=1024 / BK
#define STG_ROWS (BM + BN)            // 384: A rows | B rows
#define STAGE_B (STG_ROWS * SST * 2)  // 30720
#define SMEM_BYTES (STAGES * STAGE_B) // 122880

__device__ __forceinline__ void mma16816(float c[4], uint32_t a0, uint32_t a1,
                                         uint32_t a2, uint32_t a3,
                                         uint32_t b0, uint32_t b1) {
    asm volatile(
        "mma.sync.aligned.m16n8k16.row.col.f32.f16.f16.f32 "
        "{%0,%1,%2,%3}, {%4,%5,%6,%7}, {%8,%9}, {%0,%1,%2,%3};\n"
        : "+f"(c[0]), "+f"(c[1]), "+f"(c[2]), "+f"(c[3])
        : "r"(a0), "r"(a1), "r"(a2), "r"(a3), "r"(b0), "r"(b1));
}

__device__ __forceinline__ void ldsm4(uint32_t& r0, uint32_t& r1,
                                      uint32_t& r2, uint32_t& r3, uint32_t a) {
    asm volatile("ldmatrix.sync.aligned.m8n8.x4.shared.b16 {%0,%1,%2,%3}, [%4];"
                 : "=r"(r0), "=r"(r1), "=r"(r2), "=r"(r3) : "r"(a));
}

__device__ __forceinline__ void cp16(uint32_t s, const void* g) {
    asm volatile("cp.async.cg.shared.global [%0], [%1], 16;" :: "r"(s), "l"(g));
}

__global__ void __launch_bounds__(256, 1) gemm_kernel(GemmArgs args) {
    extern __shared__ __half smem[];

    const int z = blockIdx.z;
    const __half* __restrict__ A   = args.A;
    const __half* __restrict__ Bw  = args.Bm[z];
    const float* __restrict__ bias = args.bias[z];
    float* __restrict__ C          = args.C[z];

    const int bn  = blockIdx.x * BN;
    const int bm  = blockIdx.y * BM;
    const int tid = threadIdx.x;
    const int warp = tid >> 5, lane = tid & 31;
    const int wm = (warp >> 1) * 64;   // 0/64/128/192
    const int wn = (warp & 1) * 64;    // 0/64

    const uint32_t sbase = (uint32_t)__cvta_generic_to_shared(smem);
    auto srow = [&](int s, int r, int c) -> uint32_t {
        return sbase + (uint32_t)(((s * STG_ROWS + r) * SST + c) * 2);
    };

    // ldmatrix lane address components
    const int alr = lane & 15, alc = (lane >> 4) * 8;
    const int blr = ((lane >> 4) & 1) * 8 + (lane & 7);
    const int blc = ((lane >> 3) & 1) * 8;

    auto issue = [&](int kt, int s) {
        const int kc = kt * BK;
#pragma unroll
        for (int j = 0; j < 6; j++) {
            const int c   = tid + 256 * j;        // 0..1535 16B-chunks
            const int row = c >> 2;               // 4 chunks per 32-half row
            const int c8  = (c & 3) * 8;
            const __half* g = (row < BM)
                ? A  + (size_t)(bm + row) * DD + kc + c8
                : Bw + (size_t)(bn + row - BM) * DD + kc + c8;
            cp16(srow(s, row, c8), g);
        }
        asm volatile("cp.async.commit_group;");
    };

    float acc[4][8][4];
#pragma unroll
    for (int i = 0; i < 4; i++)
#pragma unroll
        for (int j = 0; j < 8; j++)
#pragma unroll
            for (int r = 0; r < 4; r++) acc[i][j][r] = 0.f;

    issue(0, 0); issue(1, 1); issue(2, 2);

    for (int kt = 0; kt < NKT; kt++) {
        const int s = kt & 3;
        if (kt + 3 < NKT) { asm volatile("cp.async.wait_group 2;"); }
        else              { asm volatile("cp.async.wait_group 0;"); }
        __syncthreads();
        if (kt + 3 < NKT) issue(kt + 3, (kt + 3) & 3);

#pragma unroll
        for (int kk = 0; kk < 2; kk++) {
            const int k0 = kk * 16;
            uint32_t a[4][4], b[8][2];
#pragma unroll
            for (int i = 0; i < 4; i++)
                ldsm4(a[i][0], a[i][1], a[i][2], a[i][3],
                      srow(s, wm + i * 16 + alr, k0 + alc));
#pragma unroll
            for (int jp = 0; jp < 4; jp++)
                ldsm4(b[2 * jp][0], b[2 * jp][1],
                      b[2 * jp + 1][0], b[2 * jp + 1][1],
                      srow(s, BM + wn + jp * 16 + blr, k0 + blc));
#pragma unroll
            for (int i = 0; i < 4; i++)
#pragma unroll
                for (int j = 0; j < 8; j++)
                    mma16816(acc[i][j], a[i][0], a[i][1], a[i][2], a[i][3],
                             b[j][0], b[j][1]);
        }
    }

    // epilogue: fp32 stores + bias
    const int qr = lane >> 2, qc = lane & 3;
#pragma unroll
    for (int i = 0; i < 4; i++) {
#pragma unroll
        for (int j = 0; j < 8; j++) {
            const int row = bm + wm + i * 16 + qr;
            const int col = bn + wn + j * 8 + qc * 2;
            const float b0 = bias[col], b1 = bias[col + 1];
            float2 v0 = make_float2(acc[i][j][0] + b0, acc[i][j][1] + b1);
            float2 v1 = make_float2(acc[i][j][2] + b0, acc[i][j][3] + b1);
            *(float2*)&C[(size_t)row * DD + col]       = v0;
            *(float2*)&C[(size_t)(row + 8) * DD + col] = v1;
        }
    }
}

// ---------------------------------------------------------------------------
// Per-token attention over the HEAD axis. One warp per token; emits fp16 ctx.
// ---------------------------------------------------------------------------
__global__ void __launch_bounds__(64) attn_kernel(
    const float* __restrict__ Q, const float* __restrict__ K,
    const float* __restrict__ V, __half* __restrict__ Ch) {
    __shared__ float sQ[2][DD], sK[2][DD], sV[2][DD];
    __shared__ float sS[2][HH][HH];

    const int warp = threadIdx.x >> 5, lane = threadIdx.x & 31;
    const size_t t = (size_t)blockIdx.x * 2 + warp;

    const float4* q4 = (const float4*)(Q + t * DD);
    const float4* k4 = (const float4*)(K + t * DD);
    const float4* v4 = (const float4*)(V + t * DD);
#pragma unroll
    for (int i = lane; i < DD / 4; i += 32) {
        ((float4*)sQ[warp])[i] = q4[i];
        ((float4*)sK[warp])[i] = k4[i];
        ((float4*)sV[warp])[i] = v4[i];
    }
    __syncwarp();

    for (int p = lane; p < HH * HH; p += 32) {
        const int h = p >> 4, g = p & 15;
        const float* q = &sQ[warp][h * DHH];
        const float* k = &sK[warp][g * DHH];
        float s = 0.f;
#pragma unroll
        for (int d = 0; d < DHH; d++) s += q[d] * k[d];
        sS[warp][h][g] = s * 0.125f;   // 1/sqrt(64)
    }
    __syncwarp();

    if (lane < HH) {
        float mx = -1e30f;
#pragma unroll
        for (int g = 0; g < HH; g++) mx = fmaxf(mx, sS[warp][lane][g]);
        float sum = 0.f;
#pragma unroll
        for (int g = 0; g < HH; g++) {
            float e = expf(sS[warp][lane][g] - mx);
            sS[warp][lane][g] = e;
            sum += e;
        }
        const float inv = 1.f / sum;
#pragma unroll
        for (int g = 0; g < HH; g++) sS[warp][lane][g] *= inv;
    }
    __syncwarp();

    __half* out = Ch + t * DD;
    for (int o2 = lane; o2 < DD / 2; o2 += 32) {
        const int o = o2 * 2;
        const int h = o >> 6, d = o & 63;
        float c0 = 0.f, c1 = 0.f;
#pragma unroll
        for (int g = 0; g < HH; g++) {
            c0 += sS[warp][h][g] * sV[warp][g * DHH + d];
            c1 += sS[warp][h][g] * sV[warp][g * DHH + d + 1];
        }
        ((__half2*)out)[o2] = __floats2half2_rn(c0, c1);
    }
}

// ---------------------------------------------------------------------------
// Launch
// ---------------------------------------------------------------------------
extern "C" void kernel_launch(void* const* d_in, const int* in_sizes, int n_in,
                              void* d_out, int out_size) {
    (void)in_sizes; (void)n_in; (void)out_size;
    const float* x  = (const float*)d_in[0];
    const float* wq = (const float*)d_in[1];
    const float* bq = (const float*)d_in[2];
    const float* wk = (const float*)d_in[3];
    const float* bk = (const float*)d_in[4];
    const float* wv = (const float*)d_in[5];
    const float* bv = (const float*)d_in[6];
    const float* wo = (const float*)d_in[7];
    const float* bo = (const float*)d_in[8];
    float* out = (float*)d_out;

    __half *Xh, *Wh, *Ch;
    float *Q, *K, *V;
    cudaGetSymbolAddress((void**)&Xh, g_Xh);
    cudaGetSymbolAddress((void**)&Wh, g_Wh);
    cudaGetSymbolAddress((void**)&Ch, g_Ch);
    cudaGetSymbolAddress((void**)&Q,  g_Q);
    cudaGetSymbolAddress((void**)&K,  g_K);
    cudaGetSymbolAddress((void**)&V,  g_V);
    const size_t WS = (size_t)DD * DD;

    cudaFuncSetAttribute(gemm_kernel,
                         cudaFuncAttributeMaxDynamicSharedMemorySize, SMEM_BYTES);

    // 1) converts to fp16
    cvt_kernel<<<(size_t)TT * DD / 4 / 256, 256>>>(x, Xh);
    cvt_kernel<<<(size_t)DD * DD / 4 / 256, 256>>>(wq, Wh + 0 * WS);
    cvt_kernel<<<(size_t)DD * DD / 4 / 256, 256>>>(wk, Wh + 1 * WS);
    cvt_kernel<<<(size_t)DD * DD / 4 / 256, 256>>>(wv, Wh + 2 * WS);
    cvt_kernel<<<(size_t)DD * DD / 4 / 256, 256>>>(wo, Wh + 3 * WS);

    // 2) fused QKV GEMMs (z = q/k/v)
    GemmArgs ga;
    ga.A = Xh;
    ga.Bm[0] = Wh + 0 * WS; ga.Bm[1] = Wh + 1 * WS; ga.Bm[2] = Wh + 2 * WS;
    ga.bias[0] = bq; ga.bias[1] = bk; ga.bias[2] = bv;
    ga.C[0] = Q; ga.C[1] = K; ga.C[2] = V;
    gemm_kernel<<<dim3(DD / BN, TT / BM, 3), 256, SMEM_BYTES>>>(ga);

    // 3) per-token head-axis attention -> fp16 ctx
    attn_kernel<<<TT / 2, 64>>>(Q, K, V, Ch);

    // 4) output projection
    GemmArgs go;
    go.A = Ch;
    go.Bm[0] = Wh + 3 * WS; go.Bm[1] = go.Bm[0]; go.Bm[2] = go.Bm[0];
    go.bias[0] = bo; go.bias[1] = bo; go.bias[2] = bo;
    go.C[0] = out; go.C[1] = out; go.C[2] = out;
    gemm_kernel<<<dim3(DD / BN, TT / BM, 1), 256, SMEM_BYTES>>>(go);
}

// round 10
// speedup vs baseline: 5.9839x; 1.1199x over previous
#include <cuda_runtime.h>
#include <cuda_fp16.h>
#include <cstdint>

// Problem dims
#define BB   8
#define SS   4096
#define DD   1024
#define HH   16
#define DHH  64
#define TT   (BB*SS)      // 32768 tokens

// ---------------------------------------------------------------------------
// Scratch (static __device__ — no allocations allowed)
// ---------------------------------------------------------------------------
__device__ __half g_Xh[(size_t)TT * DD];          // x fp16        64 MiB
__device__ __half g_Wh[4][(size_t)DD * DD];       // weights fp16   8 MiB
__device__ float  g_Q [(size_t)TT * DD];
__device__ float  g_K [(size_t)TT * DD];
__device__ float  g_V [(size_t)TT * DD];
__device__ __half g_Ch[(size_t)TT * DD];          // ctx fp16      64 MiB

// ---------------------------------------------------------------------------
// Fused fp32 -> fp16 convert: x (32768 blocks) + 4 weights (1024 blocks each)
// ---------------------------------------------------------------------------
struct CvtArgs {
    const float* x; const float* w[4];
    __half* xh; __half* wh;       // wh: 4 matrices contiguous
};

#define XBLKS 32768
#define WBLKS 1024

__global__ void __launch_bounds__(256) cvt_kernel(CvtArgs ca) {
    const int bid = blockIdx.x;
    const float* src; __half* dst; size_t i;
    if (bid < XBLKS) {
        i = (size_t)bid * 256 + threadIdx.x;
        src = ca.x; dst = ca.xh;
    } else {
        const int m = (bid - XBLKS) >> 10;
        i = (size_t)((bid - XBLKS) & 1023) * 256 + threadIdx.x;
        src = ca.w[m]; dst = ca.wh + (size_t)m * DD * DD;
    }
    float4 v = ((const float4*)src)[i];
    ((__half2*)dst)[i * 2]     = __floats2half2_rn(v.x, v.y);
    ((__half2*)dst)[i * 2 + 1] = __floats2half2_rn(v.z, v.w);
}

// ---------------------------------------------------------------------------
// fp16 NT GEMM:  C[M,N] = A[M,K]*B[N,K]^T + bias, fp32 accumulate.
// CTA tile 128x128 (8 warps, warp 64x32), BK=32, 4-stage cp.async pipeline,
// 2 CTAs/SM (4 warps/SMSP for HMMA latency hiding). blockIdx.z selects q/k/v.
// ---------------------------------------------------------------------------
struct GemmArgs {
    const __half* A;
    const __half* Bm[3];
    const float*  bias[3];
    float*        C[3];
};

#define BM 128
#define BN 128
#define BK 32
#define SST 40                        // smem row stride (halfs)
#define STAGES 4
#define NKT 32                        // K=1024 / BK
#define STG_ROWS (BM + BN)            // 256: A rows | B rows
#define STAGE_B (STG_ROWS * SST * 2)  // 20480
#define SMEM_BYTES (STAGES * STAGE_B) // 81920

__device__ __forceinline__ void mma16816(float c[4], uint32_t a0, uint32_t a1,
                                         uint32_t a2, uint32_t a3,
                                         uint32_t b0, uint32_t b1) {
    asm volatile(
        "mma.sync.aligned.m16n8k16.row.col.f32.f16.f16.f32 "
        "{%0,%1,%2,%3}, {%4,%5,%6,%7}, {%8,%9}, {%0,%1,%2,%3};\n"
        : "+f"(c[0]), "+f"(c[1]), "+f"(c[2]), "+f"(c[3])
        : "r"(a0), "r"(a1), "r"(a2), "r"(a3), "r"(b0), "r"(b1));
}

__device__ __forceinline__ void ldsm4(uint32_t& r0, uint32_t& r1,
                                      uint32_t& r2, uint32_t& r3, uint32_t a) {
    asm volatile("ldmatrix.sync.aligned.m8n8.x4.shared.b16 {%0,%1,%2,%3}, [%4];"
                 : "=r"(r0), "=r"(r1), "=r"(r2), "=r"(r3) : "r"(a));
}

__device__ __forceinline__ void cp16(uint32_t s, const void* g) {
    asm volatile("cp.async.cg.shared.global [%0], [%1], 16;" :: "r"(s), "l"(g));
}

__global__ void __launch_bounds__(256, 2) gemm_kernel(GemmArgs args) {
    extern __shared__ __half smem[];

    const int z = blockIdx.z;
    const __half* __restrict__ A   = args.A;
    const __half* __restrict__ Bw  = args.Bm[z];
    const float* __restrict__ bias = args.bias[z];
    float* __restrict__ C          = args.C[z];

    const int bn  = blockIdx.x * BN;
    const int bm  = blockIdx.y * BM;
    const int tid = threadIdx.x;
    const int warp = tid >> 5, lane = tid & 31;
    const int wm = (warp >> 2) * 64;   // 0/64
    const int wn = (warp & 3) * 32;    // 0/32/64/96

    const uint32_t sbase = (uint32_t)__cvta_generic_to_shared(smem);
    auto srow = [&](int s, int r, int c) -> uint32_t {
        return sbase + (uint32_t)(((s * STG_ROWS + r) * SST + c) * 2);
    };

    // ldmatrix lane address components
    const int alr = lane & 15, alc = (lane >> 4) * 8;     // A x4 (16 rows)
    const int blr = ((lane >> 4) & 1) * 8 + (lane & 7);   // B x4
    const int blc = ((lane >> 3) & 1) * 8;

    // loader: 1024 16B-chunks per stage, 4 per thread
    auto issue = [&](int kt, int s) {
        const int kc = kt * BK;
#pragma unroll
        for (int j = 0; j < 4; j++) {
            const int c   = tid + 256 * j;        // 0..1023
            const int row = c >> 2;               // 4 chunks per 32-half row
            const int c8  = (c & 3) * 8;
            const __half* g = (row < BM)
                ? A  + (size_t)(bm + row) * DD + kc + c8
                : Bw + (size_t)(bn + row - BM) * DD + kc + c8;
            cp16(srow(s, row, c8), g);
        }
        asm volatile("cp.async.commit_group;");
    };

    float acc[4][4][4];
#pragma unroll
    for (int i = 0; i < 4; i++)
#pragma unroll
        for (int j = 0; j < 4; j++)
#pragma unroll
            for (int r = 0; r < 4; r++) acc[i][j][r] = 0.f;

    issue(0, 0); issue(1, 1); issue(2, 2);

    for (int kt = 0; kt < NKT; kt++) {
        const int s = kt & 3;
        if (kt + 3 < NKT) { asm volatile("cp.async.wait_group 2;"); }
        else              { asm volatile("cp.async.wait_group 0;"); }
        __syncthreads();
        if (kt + 3 < NKT) issue(kt + 3, (kt + 3) & 3);

#pragma unroll
        for (int kk = 0; kk < 2; kk++) {
            const int k0 = kk * 16;
            uint32_t a[4][4], b[4][2];
#pragma unroll
            for (int i = 0; i < 4; i++)
                ldsm4(a[i][0], a[i][1], a[i][2], a[i][3],
                      srow(s, wm + i * 16 + alr, k0 + alc));
#pragma unroll
            for (int jp = 0; jp < 2; jp++)
                ldsm4(b[2 * jp][0], b[2 * jp][1],
                      b[2 * jp + 1][0], b[2 * jp + 1][1],
                      srow(s, BM + wn + jp * 16 + blr, k0 + blc));
#pragma unroll
            for (int i = 0; i < 4; i++)
#pragma unroll
                for (int j = 0; j < 4; j++)
                    mma16816(acc[i][j], a[i][0], a[i][1], a[i][2], a[i][3],
                             b[j][0], b[j][1]);
        }
    }

    // epilogue: fp32 stores + bias
    const int qr = lane >> 2, qc = lane & 3;
#pragma unroll
    for (int i = 0; i < 4; i++) {
#pragma unroll
        for (int j = 0; j < 4; j++) {
            const int row = bm + wm + i * 16 + qr;
            const int col = bn + wn + j * 8 + qc * 2;
            const float b0 = bias[col], b1 = bias[col + 1];
            float2 v0 = make_float2(acc[i][j][0] + b0, acc[i][j][1] + b1);
            float2 v1 = make_float2(acc[i][j][2] + b0, acc[i][j][3] + b1);
            *(float2*)&C[(size_t)row * DD + col]       = v0;
            *(float2*)&C[(size_t)(row + 8) * DD + col] = v1;
        }
    }
}

// ---------------------------------------------------------------------------
// Per-token attention over the HEAD axis. One warp per token; emits fp16 ctx.
// ---------------------------------------------------------------------------
__global__ void __launch_bounds__(64) attn_kernel(
    const float* __restrict__ Q, const float* __restrict__ K,
    const float* __restrict__ V, __half* __restrict__ Ch) {
    __shared__ float sQ[2][DD], sK[2][DD], sV[2][DD];
    __shared__ float sS[2][HH][HH];

    const int warp = threadIdx.x >> 5, lane = threadIdx.x & 31;
    const size_t t = (size_t)blockIdx.x * 2 + warp;

    const float4* q4 = (const float4*)(Q + t * DD);
    const float4* k4 = (const float4*)(K + t * DD);
    const float4* v4 = (const float4*)(V + t * DD);
#pragma unroll
    for (int i = lane; i < DD / 4; i += 32) {
        ((float4*)sQ[warp])[i] = q4[i];
        ((float4*)sK[warp])[i] = k4[i];
        ((float4*)sV[warp])[i] = v4[i];
    }
    __syncwarp();

    for (int p = lane; p < HH * HH; p += 32) {
        const int h = p >> 4, g = p & 15;
        const float* q = &sQ[warp][h * DHH];
        const float* k = &sK[warp][g * DHH];
        float s = 0.f;
#pragma unroll
        for (int d = 0; d < DHH; d++) s += q[d] * k[d];
        sS[warp][h][g] = s * 0.125f;   // 1/sqrt(64)
    }
    __syncwarp();

    if (lane < HH) {
        float mx = -1e30f;
#pragma unroll
        for (int g = 0; g < HH; g++) mx = fmaxf(mx, sS[warp][lane][g]);
        float sum = 0.f;
#pragma unroll
        for (int g = 0; g < HH; g++) {
            float e = expf(sS[warp][lane][g] - mx);
            sS[warp][lane][g] = e;
            sum += e;
        }
        const float inv = 1.f / sum;
#pragma unroll
        for (int g = 0; g < HH; g++) sS[warp][lane][g] *= inv;
    }
    __syncwarp();

    __half* out = Ch + t * DD;
    for (int o2 = lane; o2 < DD / 2; o2 += 32) {
        const int o = o2 * 2;
        const int h = o >> 6, d = o & 63;
        float c0 = 0.f, c1 = 0.f;
#pragma unroll
        for (int g = 0; g < HH; g++) {
            c0 += sS[warp][h][g] * sV[warp][g * DHH + d];
            c1 += sS[warp][h][g] * sV[warp][g * DHH + d + 1];
        }
        ((__half2*)out)[o2] = __floats2half2_rn(c0, c1);
    }
}

// ---------------------------------------------------------------------------
// Launch
// ---------------------------------------------------------------------------
extern "C" void kernel_launch(void* const* d_in, const int* in_sizes, int n_in,
                              void* d_out, int out_size) {
    (void)in_sizes; (void)n_in; (void)out_size;
    const float* x  = (const float*)d_in[0];
    const float* wq = (const float*)d_in[1];
    const float* bq = (const float*)d_in[2];
    const float* wk = (const float*)d_in[3];
    const float* bk = (const float*)d_in[4];
    const float* wv = (const float*)d_in[5];
    const float* bv = (const float*)d_in[6];
    const float* wo = (const float*)d_in[7];
    const float* bo = (const float*)d_in[8];
    float* out = (float*)d_out;

    __half *Xh, *Wh, *Ch;
    float *Q, *K, *V;
    cudaGetSymbolAddress((void**)&Xh, g_Xh);
    cudaGetSymbolAddress((void**)&Wh, g_Wh);
    cudaGetSymbolAddress((void**)&Ch, g_Ch);
    cudaGetSymbolAddress((void**)&Q,  g_Q);
    cudaGetSymbolAddress((void**)&K,  g_K);
    cudaGetSymbolAddress((void**)&V,  g_V);
    const size_t WS = (size_t)DD * DD;

    cudaFuncSetAttribute(gemm_kernel,
                         cudaFuncAttributeMaxDynamicSharedMemorySize, SMEM_BYTES);

    // 1) fused converts to fp16 (x + 4 weights in one launch)
    CvtArgs ca;
    ca.x = x; ca.w[0] = wq; ca.w[1] = wk; ca.w[2] = wv; ca.w[3] = wo;
    ca.xh = Xh; ca.wh = Wh;
    cvt_kernel<<<XBLKS + 4 * WBLKS, 256>>>(ca);

    // 2) fused QKV GEMMs (z = q/k/v)
    GemmArgs ga;
    ga.A = Xh;
    ga.Bm[0] = Wh + 0 * WS; ga.Bm[1] = Wh + 1 * WS; ga.Bm[2] = Wh + 2 * WS;
    ga.bias[0] = bq; ga.bias[1] = bk; ga.bias[2] = bv;
    ga.C[0] = Q; ga.C[1] = K; ga.C[2] = V;
    gemm_kernel<<<dim3(DD / BN, TT / BM, 3), 256, SMEM_BYTES>>>(ga);

    // 3) per-token head-axis attention -> fp16 ctx
    attn_kernel<<<TT / 2, 64>>>(Q, K, V, Ch);

    // 4) output projection
    GemmArgs go;
    go.A = Ch;
    go.Bm[0] = Wh + 3 * WS; go.Bm[1] = go.Bm[0]; go.Bm[2] = go.Bm[0];
    go.bias[0] = bo; go.bias[1] = bo; go.bias[2] = bo;
    go.C[0] = out; go.C[1] = out; go.C[2] = out;
    gemm_kernel<<<dim3(DD / BN, TT / BM, 1), 256, SMEM_BYTES>>>(go);
}

// round 11
// speedup vs baseline: 6.5406x; 1.0930x over previous
#include <cuda_runtime.h>
#include <cuda_fp16.h>
#include <cstdint>

// Problem dims
#define BB   8
#define SS   4096
#define DD   1024
#define HH   16
#define DHH  64
#define TT   (BB*SS)      // 32768 tokens

// ---------------------------------------------------------------------------
// Scratch (static __device__ — no allocations allowed)
// ---------------------------------------------------------------------------
__device__ __half g_Xh[(size_t)TT * DD];          // x fp16        64 MiB
__device__ __half g_Wh[4][(size_t)DD * DD];       // weights fp16   8 MiB
__device__ float  g_Q [(size_t)TT * DD];
__device__ float  g_K [(size_t)TT * DD];
__device__ float  g_V [(size_t)TT * DD];
__device__ __half g_Ch[(size_t)TT * DD];          // ctx fp16      64 MiB

// ---------------------------------------------------------------------------
// Fused fp32 -> fp16 convert, 4 float4 per thread (MLP=4 hides DRAM latency).
// x: 8192 blocks; each weight: 256 blocks.
// ---------------------------------------------------------------------------
struct CvtArgs {
    const float* x; const float* w[4];
    __half* xh; __half* wh;       // wh: 4 matrices contiguous
};

#define XBLKS 8192
#define WBLKS 256

__global__ void __launch_bounds__(256) cvt_kernel(CvtArgs ca) {
    const int bid = blockIdx.x;
    const float* src; __half* dst; size_t base;
    if (bid < XBLKS) {
        base = (size_t)bid * 1024;
        src = ca.x; dst = ca.xh;
    } else {
        const int m = (bid - XBLKS) >> 8;
        base = (size_t)((bid - XBLKS) & 255) * 1024;
        src = ca.w[m]; dst = ca.wh + (size_t)m * DD * DD;
    }
    float4 v[4];
#pragma unroll
    for (int j = 0; j < 4; j++)
        v[j] = ((const float4*)src)[base + threadIdx.x + 256 * j];
#pragma unroll
    for (int j = 0; j < 4; j++) {
        const size_t i = base + threadIdx.x + 256 * j;
        ((__half2*)dst)[i * 2]     = __floats2half2_rn(v[j].x, v[j].y);
        ((__half2*)dst)[i * 2 + 1] = __floats2half2_rn(v[j].z, v[j].w);
    }
}

// ---------------------------------------------------------------------------
// fp16 NT GEMM:  C[M,N] = A[M,K]*B[N,K]^T + bias, fp32 accumulate.
// CTA tile 128x128 (8 warps, warp 64x32), BK=64, 3-stage cp.async pipeline,
// 2 CTAs/SM (4 warps/SMSP). One __syncthreads per 64-deep k-chunk.
// ---------------------------------------------------------------------------
struct GemmArgs {
    const __half* A;
    const __half* Bm[3];
    const float*  bias[3];
    float*        C[3];
};

#define BM 128
#define BN 128
#define BK 64
#define SST 72                        // smem row stride (halfs)
#define STAGES 3
#define NKT 16                        // K=1024 / BK
#define STG_ROWS (BM + BN)            // 256: A rows | B rows
#define STAGE_B (STG_ROWS * SST * 2)  // 36864
#define SMEM_BYTES (STAGES * STAGE_B) // 110592

__device__ __forceinline__ void mma16816(float c[4], uint32_t a0, uint32_t a1,
                                         uint32_t a2, uint32_t a3,
                                         uint32_t b0, uint32_t b1) {
    asm volatile(
        "mma.sync.aligned.m16n8k16.row.col.f32.f16.f16.f32 "
        "{%0,%1,%2,%3}, {%4,%5,%6,%7}, {%8,%9}, {%0,%1,%2,%3};\n"
        : "+f"(c[0]), "+f"(c[1]), "+f"(c[2]), "+f"(c[3])
        : "r"(a0), "r"(a1), "r"(a2), "r"(a3), "r"(b0), "r"(b1));
}

__device__ __forceinline__ void ldsm4(uint32_t& r0, uint32_t& r1,
                                      uint32_t& r2, uint32_t& r3, uint32_t a) {
    asm volatile("ldmatrix.sync.aligned.m8n8.x4.shared.b16 {%0,%1,%2,%3}, [%4];"
                 : "=r"(r0), "=r"(r1), "=r"(r2), "=r"(r3) : "r"(a));
}

__device__ __forceinline__ void cp16(uint32_t s, const void* g) {
    asm volatile("cp.async.cg.shared.global [%0], [%1], 16;" :: "r"(s), "l"(g));
}

__global__ void __launch_bounds__(256, 2) gemm_kernel(GemmArgs args) {
    extern __shared__ __half smem[];

    const int z = blockIdx.z;
    const __half* __restrict__ A   = args.A;
    const __half* __restrict__ Bw  = args.Bm[z];
    const float* __restrict__ bias = args.bias[z];
    float* __restrict__ C          = args.C[z];

    const int bn  = blockIdx.x * BN;
    const int bm  = blockIdx.y * BM;
    const int tid = threadIdx.x;
    const int warp = tid >> 5, lane = tid & 31;
    const int wm = (warp >> 2) * 64;   // 0/64
    const int wn = (warp & 3) * 32;    // 0/32/64/96

    const uint32_t sbase = (uint32_t)__cvta_generic_to_shared(smem);
    auto srow = [&](int s, int r, int c) -> uint32_t {
        return sbase + (uint32_t)(((s * STG_ROWS + r) * SST + c) * 2);
    };

    // ldmatrix lane address components
    const int alr = lane & 15, alc = (lane >> 4) * 8;     // A x4 (16 rows)
    const int blr = ((lane >> 4) & 1) * 8 + (lane & 7);   // B x4
    const int blc = ((lane >> 3) & 1) * 8;

    // loader: 2048 16B-chunks per stage (256 rows x 128B), 8 per thread
    auto issue = [&](int kt, int s) {
        const int kc = kt * BK;
#pragma unroll
        for (int j = 0; j < 8; j++) {
            const int c   = tid + 256 * j;        // 0..2047
            const int row = c >> 3;               // 8 chunks per 64-half row
            const int c8  = (c & 7) * 8;
            const __half* g = (row < BM)
                ? A  + (size_t)(bm + row) * DD + kc + c8
                : Bw + (size_t)(bn + row - BM) * DD + kc + c8;
            cp16(srow(s, row, c8), g);
        }
        asm volatile("cp.async.commit_group;");
    };

    float acc[4][4][4];
#pragma unroll
    for (int i = 0; i < 4; i++)
#pragma unroll
        for (int j = 0; j < 4; j++)
#pragma unroll
            for (int r = 0; r < 4; r++) acc[i][j][r] = 0.f;

    issue(0, 0); issue(1, 1);

    for (int kt = 0; kt < NKT; kt++) {
        const int s = kt % STAGES;
        if (kt + 2 < NKT) { asm volatile("cp.async.wait_group 1;"); }
        else              { asm volatile("cp.async.wait_group 0;"); }
        __syncthreads();
        if (kt + 2 < NKT) issue(kt + 2, (kt + 2) % STAGES);

#pragma unroll
        for (int kk = 0; kk < 4; kk++) {
            const int k0 = kk * 16;
            uint32_t a[4][4], b[4][2];
#pragma unroll
            for (int i = 0; i < 4; i++)
                ldsm4(a[i][0], a[i][1], a[i][2], a[i][3],
                      srow(s, wm + i * 16 + alr, k0 + alc));
#pragma unroll
            for (int jp = 0; jp < 2; jp++)
                ldsm4(b[2 * jp][0], b[2 * jp][1],
                      b[2 * jp + 1][0], b[2 * jp + 1][1],
                      srow(s, BM + wn + jp * 16 + blr, k0 + blc));
#pragma unroll
            for (int i = 0; i < 4; i++)
#pragma unroll
                for (int j = 0; j < 4; j++)
                    mma16816(acc[i][j], a[i][0], a[i][1], a[i][2], a[i][3],
                             b[j][0], b[j][1]);
        }
    }

    // epilogue: fp32 stores + bias
    const int qr = lane >> 2, qc = lane & 3;
#pragma unroll
    for (int i = 0; i < 4; i++) {
#pragma unroll
        for (int j = 0; j < 4; j++) {
            const int row = bm + wm + i * 16 + qr;
            const int col = bn + wn + j * 8 + qc * 2;
            const float b0 = bias[col], b1 = bias[col + 1];
            float2 v0 = make_float2(acc[i][j][0] + b0, acc[i][j][1] + b1);
            float2 v1 = make_float2(acc[i][j][2] + b0, acc[i][j][3] + b1);
            *(float2*)&C[(size_t)row * DD + col]       = v0;
            *(float2*)&C[(size_t)(row + 8) * DD + col] = v1;
        }
    }
}

// ---------------------------------------------------------------------------
// Per-token attention over the HEAD axis. One warp per token; emits fp16 ctx.
// ---------------------------------------------------------------------------
__global__ void __launch_bounds__(64) attn_kernel(
    const float* __restrict__ Q, const float* __restrict__ K,
    const float* __restrict__ V, __half* __restrict__ Ch) {
    __shared__ float sQ[2][DD], sK[2][DD], sV[2][DD];
    __shared__ float sS[2][HH][HH];

    const int warp = threadIdx.x >> 5, lane = threadIdx.x & 31;
    const size_t t = (size_t)blockIdx.x * 2 + warp;

    const float4* q4 = (const float4*)(Q + t * DD);
    const float4* k4 = (const float4*)(K + t * DD);
    const float4* v4 = (const float4*)(V + t * DD);
#pragma unroll
    for (int i = lane; i < DD / 4; i += 32) {
        ((float4*)sQ[warp])[i] = q4[i];
        ((float4*)sK[warp])[i] = k4[i];
        ((float4*)sV[warp])[i] = v4[i];
    }
    __syncwarp();

    for (int p = lane; p < HH * HH; p += 32) {
        const int h = p >> 4, g = p & 15;
        const float* q = &sQ[warp][h * DHH];
        const float* k = &sK[warp][g * DHH];
        float s = 0.f;
#pragma unroll
        for (int d = 0; d < DHH; d++) s += q[d] * k[d];
        sS[warp][h][g] = s * 0.125f;   // 1/sqrt(64)
    }
    __syncwarp();

    if (lane < HH) {
        float mx = -1e30f;
#pragma unroll
        for (int g = 0; g < HH; g++) mx = fmaxf(mx, sS[warp][lane][g]);
        float sum = 0.f;
#pragma unroll
        for (int g = 0; g < HH; g++) {
            float e = expf(sS[warp][lane][g] - mx);
            sS[warp][lane][g] = e;
            sum += e;
        }
        const float inv = 1.f / sum;
#pragma unroll
        for (int g = 0; g < HH; g++) sS[warp][lane][g] *= inv;
    }
    __syncwarp();

    __half* out = Ch + t * DD;
    for (int o2 = lane; o2 < DD / 2; o2 += 32) {
        const int o = o2 * 2;
        const int h = o >> 6, d = o & 63;
        float c0 = 0.f, c1 = 0.f;
#pragma unroll
        for (int g = 0; g < HH; g++) {
            c0 += sS[warp][h][g] * sV[warp][g * DHH + d];
            c1 += sS[warp][h][g] * sV[warp][g * DHH + d + 1];
        }
        ((__half2*)out)[o2] = __floats2half2_rn(c0, c1);
    }
}

// ---------------------------------------------------------------------------
// Launch
// ---------------------------------------------------------------------------
extern "C" void kernel_launch(void* const* d_in, const int* in_sizes, int n_in,
                              void* d_out, int out_size) {
    (void)in_sizes; (void)n_in; (void)out_size;
    const float* x  = (const float*)d_in[0];
    const float* wq = (const float*)d_in[1];
    const float* bq = (const float*)d_in[2];
    const float* wk = (const float*)d_in[3];
    const float* bk = (const float*)d_in[4];
    const float* wv = (const float*)d_in[5];
    const float* bv = (const float*)d_in[6];
    const float* wo = (const float*)d_in[7];
    const float* bo = (const float*)d_in[8];
    float* out = (float*)d_out;

    __half *Xh, *Wh, *Ch;
    float *Q, *K, *V;
    cudaGetSymbolAddress((void**)&Xh, g_Xh);
    cudaGetSymbolAddress((void**)&Wh, g_Wh);
    cudaGetSymbolAddress((void**)&Ch, g_Ch);
    cudaGetSymbolAddress((void**)&Q,  g_Q);
    cudaGetSymbolAddress((void**)&K,  g_K);
    cudaGetSymbolAddress((void**)&V,  g_V);
    const size_t WS = (size_t)DD * DD;

    cudaFuncSetAttribute(gemm_kernel,
                         cudaFuncAttributeMaxDynamicSharedMemorySize, SMEM_BYTES);

    // 1) fused converts to fp16 (x + 4 weights in one launch, MLP=4)
    CvtArgs ca;
    ca.x = x; ca.w[0] = wq; ca.w[1] = wk; ca.w[2] = wv; ca.w[3] = wo;
    ca.xh = Xh; ca.wh = Wh;
    cvt_kernel<<<XBLKS + 4 * WBLKS, 256>>>(ca);

    // 2) fused QKV GEMMs (z = q/k/v)
    GemmArgs ga;
    ga.A = Xh;
    ga.Bm[0] = Wh + 0 * WS; ga.Bm[1] = Wh + 1 * WS; ga.Bm[2] = Wh + 2 * WS;
    ga.bias[0] = bq; ga.bias[1] = bk; ga.bias[2] = bv;
    ga.C[0] = Q; ga.C[1] = K; ga.C[2] = V;
    gemm_kernel<<<dim3(DD / BN, TT / BM, 3), 256, SMEM_BYTES>>>(ga);

    // 3) per-token head-axis attention -> fp16 ctx
    attn_kernel<<<TT / 2, 64>>>(Q, K, V, Ch);

    // 4) output projection
    GemmArgs go;
    go.A = Ch;
    go.Bm[0] = Wh + 3 * WS; go.Bm[1] = go.Bm[0]; go.Bm[2] = go.Bm[0];
    go.bias[0] = bo; go.bias[1] = bo; go.bias[2] = bo;
    go.C[0] = out; go.C[1] = out; go.C[2] = out;
    gemm_kernel<<<dim3(DD / BN, TT / BM, 1), 256, SMEM_BYTES>>>(go);
}

// round 12
// speedup vs baseline: 6.6659x; 1.0192x over previous
#include <cuda_runtime.h>
#include <cuda_fp16.h>
#include <cstdint>

// Problem dims
#define BB   8
#define SS   4096
#define DD   1024
#define HH   16
#define DHH  64
#define TT   (BB*SS)      // 32768 tokens

// ---------------------------------------------------------------------------
// Scratch (static __device__ — no allocations allowed)
// ---------------------------------------------------------------------------
__device__ __half g_Xh[(size_t)TT * DD];          // x fp16        64 MiB
__device__ __half g_Wh[4][(size_t)DD * DD];       // weights fp16   8 MiB
__device__ float  g_Q [(size_t)TT * DD];
__device__ float  g_K [(size_t)TT * DD];
__device__ float  g_V [(size_t)TT * DD];
__device__ __half g_Ch[(size_t)TT * DD];          // ctx fp16      64 MiB

// ---------------------------------------------------------------------------
// Fused fp32 -> fp16 convert, 4 float4 per thread (MLP=4 hides DRAM latency).
// ---------------------------------------------------------------------------
struct CvtArgs {
    const float* x; const float* w[4];
    __half* xh; __half* wh;       // wh: 4 matrices contiguous
};

#define XBLKS 8192
#define WBLKS 256

__global__ void __launch_bounds__(256) cvt_kernel(CvtArgs ca) {
    const int bid = blockIdx.x;
    const float* src; __half* dst; size_t base;
    if (bid < XBLKS) {
        base = (size_t)bid * 1024;
        src = ca.x; dst = ca.xh;
    } else {
        const int m = (bid - XBLKS) >> 8;
        base = (size_t)((bid - XBLKS) & 255) * 1024;
        src = ca.w[m]; dst = ca.wh + (size_t)m * DD * DD;
    }
    float4 v[4];
#pragma unroll
    for (int j = 0; j < 4; j++)
        v[j] = ((const float4*)src)[base + threadIdx.x + 256 * j];
#pragma unroll
    for (int j = 0; j < 4; j++) {
        const size_t i = base + threadIdx.x + 256 * j;
        ((__half2*)dst)[i * 2]     = __floats2half2_rn(v[j].x, v[j].y);
        ((__half2*)dst)[i * 2 + 1] = __floats2half2_rn(v[j].z, v[j].w);
    }
}

// ---------------------------------------------------------------------------
// fp16 NT GEMM:  C[M,N] = A[M,K]*B[N,K]^T + bias, fp32 accumulate.
// CTA tile 128x128 with 4 warps (warp tile 64x64), BK=64, 3-stage cp.async
// pipeline, fragment double-buffering across kk, 2 CTAs/SM.
// ---------------------------------------------------------------------------
struct GemmArgs {
    const __half* A;
    const __half* Bm[3];
    const float*  bias[3];
    float*        C[3];
};

#define BM 128
#define BN 128
#define BK 64
#define SST 72                        // smem row stride (halfs)
#define STAGES 3
#define NKT 16                        // K=1024 / BK
#define STG_ROWS (BM + BN)            // 256: A rows | B rows
#define STAGE_B (STG_ROWS * SST * 2)  // 36864
#define SMEM_BYTES (STAGES * STAGE_B) // 110592

__device__ __forceinline__ void mma16816(float c[4], uint32_t a0, uint32_t a1,
                                         uint32_t a2, uint32_t a3,
                                         uint32_t b0, uint32_t b1) {
    asm volatile(
        "mma.sync.aligned.m16n8k16.row.col.f32.f16.f16.f32 "
        "{%0,%1,%2,%3}, {%4,%5,%6,%7}, {%8,%9}, {%0,%1,%2,%3};\n"
        : "+f"(c[0]), "+f"(c[1]), "+f"(c[2]), "+f"(c[3])
        : "r"(a0), "r"(a1), "r"(a2), "r"(a3), "r"(b0), "r"(b1));
}

__device__ __forceinline__ void ldsm4(uint32_t& r0, uint32_t& r1,
                                      uint32_t& r2, uint32_t& r3, uint32_t a) {
    asm volatile("ldmatrix.sync.aligned.m8n8.x4.shared.b16 {%0,%1,%2,%3}, [%4];"
                 : "=r"(r0), "=r"(r1), "=r"(r2), "=r"(r3) : "r"(a));
}

__device__ __forceinline__ void cp16(uint32_t s, const void* g) {
    asm volatile("cp.async.cg.shared.global [%0], [%1], 16;" :: "r"(s), "l"(g));
}

__global__ void __launch_bounds__(128, 2) gemm_kernel(GemmArgs args) {
    extern __shared__ __half smem[];

    const int z = blockIdx.z;
    const __half* __restrict__ A   = args.A;
    const __half* __restrict__ Bw  = args.Bm[z];
    const float* __restrict__ bias = args.bias[z];
    float* __restrict__ C          = args.C[z];

    const int bn  = blockIdx.x * BN;
    const int bm  = blockIdx.y * BM;
    const int tid = threadIdx.x;
    const int warp = tid >> 5, lane = tid & 31;
    const int wm = (warp >> 1) * 64;   // 0/64
    const int wn = (warp & 1) * 64;    // 0/64

    const uint32_t sbase = (uint32_t)__cvta_generic_to_shared(smem);
    auto srow = [&](int s, int r, int c) -> uint32_t {
        return sbase + (uint32_t)(((s * STG_ROWS + r) * SST + c) * 2);
    };

    // ldmatrix lane address components
    const int alr = lane & 15, alc = (lane >> 4) * 8;     // A x4 (16 rows)
    const int blr = ((lane >> 4) & 1) * 8 + (lane & 7);   // B x4
    const int blc = ((lane >> 3) & 1) * 8;

    // loader: 2048 16B-chunks per stage (256 rows x 128B), 16 per thread
    auto issue = [&](int kt, int s) {
        const int kc = kt * BK;
#pragma unroll
        for (int j = 0; j < 16; j++) {
            const int c   = tid + 128 * j;        // 0..2047
            const int row = c >> 3;               // 8 chunks per 64-half row
            const int c8  = (c & 7) * 8;
            const __half* g = (row < BM)
                ? A  + (size_t)(bm + row) * DD + kc + c8
                : Bw + (size_t)(bn + row - BM) * DD + kc + c8;
            cp16(srow(s, row, c8), g);
        }
        asm volatile("cp.async.commit_group;");
    };

    float acc[4][8][4];
#pragma unroll
    for (int i = 0; i < 4; i++)
#pragma unroll
        for (int j = 0; j < 8; j++)
#pragma unroll
            for (int r = 0; r < 4; r++) acc[i][j][r] = 0.f;

    uint32_t a[2][4][4], b[2][8][2];

    auto load_frags = [&](int s, int kk, int buf) {
        const int k0 = kk * 16;
#pragma unroll
        for (int i = 0; i < 4; i++)
            ldsm4(a[buf][i][0], a[buf][i][1], a[buf][i][2], a[buf][i][3],
                  srow(s, wm + i * 16 + alr, k0 + alc));
#pragma unroll
        for (int jp = 0; jp < 4; jp++)
            ldsm4(b[buf][2 * jp][0], b[buf][2 * jp][1],
                  b[buf][2 * jp + 1][0], b[buf][2 * jp + 1][1],
                  srow(s, BM + wn + jp * 16 + blr, k0 + blc));
    };

    issue(0, 0); issue(1, 1);

    for (int kt = 0; kt < NKT; kt++) {
        const int s = kt % STAGES;
        if (kt + 2 < NKT) { asm volatile("cp.async.wait_group 1;"); }
        else              { asm volatile("cp.async.wait_group 0;"); }
        __syncthreads();
        if (kt + 2 < NKT) issue(kt + 2, (kt + 2) % STAGES);

        load_frags(s, 0, 0);
#pragma unroll
        for (int kk = 0; kk < 4; kk++) {
            const int cur = kk & 1;
            if (kk < 3) load_frags(s, kk + 1, cur ^ 1);
#pragma unroll
            for (int i = 0; i < 4; i++)
#pragma unroll
                for (int j = 0; j < 8; j++)
                    mma16816(acc[i][j],
                             a[cur][i][0], a[cur][i][1], a[cur][i][2], a[cur][i][3],
                             b[cur][j][0], b[cur][j][1]);
        }
    }

    // epilogue: fp32 stores + bias
    const int qr = lane >> 2, qc = lane & 3;
#pragma unroll
    for (int i = 0; i < 4; i++) {
#pragma unroll
        for (int j = 0; j < 8; j++) {
            const int row = bm + wm + i * 16 + qr;
            const int col = bn + wn + j * 8 + qc * 2;
            const float b0 = bias[col], b1 = bias[col + 1];
            float2 v0 = make_float2(acc[i][j][0] + b0, acc[i][j][1] + b1);
            float2 v1 = make_float2(acc[i][j][2] + b0, acc[i][j][3] + b1);
            *(float2*)&C[(size_t)row * DD + col]       = v0;
            *(float2*)&C[(size_t)(row + 8) * DD + col] = v1;
        }
    }
}

// ---------------------------------------------------------------------------
// Per-token attention over the HEAD axis. One warp per token; emits fp16 ctx.
// ---------------------------------------------------------------------------
__global__ void __launch_bounds__(64) attn_kernel(
    const float* __restrict__ Q, const float* __restrict__ K,
    const float* __restrict__ V, __half* __restrict__ Ch) {
    __shared__ float sQ[2][DD], sK[2][DD], sV[2][DD];
    __shared__ float sS[2][HH][HH];

    const int warp = threadIdx.x >> 5, lane = threadIdx.x & 31;
    const size_t t = (size_t)blockIdx.x * 2 + warp;

    const float4* q4 = (const float4*)(Q + t * DD);
    const float4* k4 = (const float4*)(K + t * DD);
    const float4* v4 = (const float4*)(V + t * DD);
#pragma unroll
    for (int i = lane; i < DD / 4; i += 32) {
        ((float4*)sQ[warp])[i] = q4[i];
        ((float4*)sK[warp])[i] = k4[i];
        ((float4*)sV[warp])[i] = v4[i];
    }
    __syncwarp();

    for (int p = lane; p < HH * HH; p += 32) {
        const int h = p >> 4, g = p & 15;
        const float* q = &sQ[warp][h * DHH];
        const float* k = &sK[warp][g * DHH];
        float s = 0.f;
#pragma unroll
        for (int d = 0; d < DHH; d++) s += q[d] * k[d];
        sS[warp][h][g] = s * 0.125f;   // 1/sqrt(64)
    }
    __syncwarp();

    if (lane < HH) {
        float mx = -1e30f;
#pragma unroll
        for (int g = 0; g < HH; g++) mx = fmaxf(mx, sS[warp][lane][g]);
        float sum = 0.f;
#pragma unroll
        for (int g = 0; g < HH; g++) {
            float e = expf(sS[warp][lane][g] - mx);
            sS[warp][lane][g] = e;
            sum += e;
        }
        const float inv = 1.f / sum;
#pragma unroll
        for (int g = 0; g < HH; g++) sS[warp][lane][g] *= inv;
    }
    __syncwarp();

    __half* out = Ch + t * DD;
    for (int o2 = lane; o2 < DD / 2; o2 += 32) {
        const int o = o2 * 2;
        const int h = o >> 6, d = o & 63;
        float c0 = 0.f, c1 = 0.f;
#pragma unroll
        for (int g = 0; g < HH; g++) {
            c0 += sS[warp][h][g] * sV[warp][g * DHH + d];
            c1 += sS[warp][h][g] * sV[warp][g * DHH + d + 1];
        }
        ((__half2*)out)[o2] = __floats2half2_rn(c0, c1);
    }
}

// ---------------------------------------------------------------------------
// Launch
// ---------------------------------------------------------------------------
extern "C" void kernel_launch(void* const* d_in, const int* in_sizes, int n_in,
                              void* d_out, int out_size) {
    (void)in_sizes; (void)n_in; (void)out_size;
    const float* x  = (const float*)d_in[0];
    const float* wq = (const float*)d_in[1];
    const float* bq = (const float*)d_in[2];
    const float* wk = (const float*)d_in[3];
    const float* bk = (const float*)d_in[4];
    const float* wv = (const float*)d_in[5];
    const float* bv = (const float*)d_in[6];
    const float* wo = (const float*)d_in[7];
    const float* bo = (const float*)d_in[8];
    float* out = (float*)d_out;

    __half *Xh, *Wh, *Ch;
    float *Q, *K, *V;
    cudaGetSymbolAddress((void**)&Xh, g_Xh);
    cudaGetSymbolAddress((void**)&Wh, g_Wh);
    cudaGetSymbolAddress((void**)&Ch, g_Ch);
    cudaGetSymbolAddress((void**)&Q,  g_Q);
    cudaGetSymbolAddress((void**)&K,  g_K);
    cudaGetSymbolAddress((void**)&V,  g_V);
    const size_t WS = (size_t)DD * DD;

    cudaFuncSetAttribute(gemm_kernel,
                         cudaFuncAttributeMaxDynamicSharedMemorySize, SMEM_BYTES);

    // 1) fused converts to fp16 (x + 4 weights in one launch, MLP=4)
    CvtArgs ca;
    ca.x = x; ca.w[0] = wq; ca.w[1] = wk; ca.w[2] = wv; ca.w[3] = wo;
    ca.xh = Xh; ca.wh = Wh;
    cvt_kernel<<<XBLKS + 4 * WBLKS, 256>>>(ca);

    // 2) fused QKV GEMMs (z = q/k/v)
    GemmArgs ga;
    ga.A = Xh;
    ga.Bm[0] = Wh + 0 * WS; ga.Bm[1] = Wh + 1 * WS; ga.Bm[2] = Wh + 2 * WS;
    ga.bias[0] = bq; ga.bias[1] = bk; ga.bias[2] = bv;
    ga.C[0] = Q; ga.C[1] = K; ga.C[2] = V;
    gemm_kernel<<<dim3(DD / BN, TT / BM, 3), 128, SMEM_BYTES>>>(ga);

    // 3) per-token head-axis attention -> fp16 ctx
    attn_kernel<<<TT / 2, 64>>>(Q, K, V, Ch);

    // 4) output projection
    GemmArgs go;
    go.A = Ch;
    go.Bm[0] = Wh + 3 * WS; go.Bm[1] = go.Bm[0]; go.Bm[2] = go.Bm[0];
    go.bias[0] = bo; go.bias[1] = bo; go.bias[2] = bo;
    go.C[0] = out; go.C[1] = out; go.C[2] = out;
    gemm_kernel<<<dim3(DD / BN, TT / BM, 1), 128, SMEM_BYTES>>>(go);
}

// round 14
// speedup vs baseline: 6.8644x; 1.0298x over previous
#include <cuda_runtime.h>
#include <cuda_fp16.h>
#include <cstdint>

// Problem dims
#define BB   8
#define SS   4096
#define DD   1024
#define HH   16
#define DHH  64
#define TT   (BB*SS)      // 32768 tokens

// ---------------------------------------------------------------------------
// Scratch (static __device__ — no allocations allowed)
// ---------------------------------------------------------------------------
__device__ __half g_Xh[(size_t)TT * DD];          // x fp16        64 MiB
__device__ __half g_Wh[4][(size_t)DD * DD];       // weights fp16   8 MiB
__device__ __half g_Qh[(size_t)TT * DD];          // q fp16        64 MiB
__device__ __half g_Kh[(size_t)TT * DD];
__device__ __half g_Vh[(size_t)TT * DD];
__device__ __half g_Ch[(size_t)TT * DD];          // ctx fp16      64 MiB

// ---------------------------------------------------------------------------
// Fused fp32 -> fp16 convert, 4 float4 per thread (MLP=4 hides DRAM latency).
// ---------------------------------------------------------------------------
struct CvtArgs {
    const float* x; const float* w[4];
    __half* xh; __half* wh;       // wh: 4 matrices contiguous
};

#define XBLKS 8192
#define WBLKS 256

__global__ void __launch_bounds__(256) cvt_kernel(CvtArgs ca) {
    const int bid = blockIdx.x;
    const float* src; __half* dst; size_t base;
    if (bid < XBLKS) {
        base = (size_t)bid * 1024;
        src = ca.x; dst = ca.xh;
    } else {
        const int m = (bid - XBLKS) >> 8;
        base = (size_t)((bid - XBLKS) & 255) * 1024;
        src = ca.w[m]; dst = ca.wh + (size_t)m * DD * DD;
    }
    float4 v[4];
#pragma unroll
    for (int j = 0; j < 4; j++)
        v[j] = ((const float4*)src)[base + threadIdx.x + 256 * j];
#pragma unroll
    for (int j = 0; j < 4; j++) {
        const size_t i = base + threadIdx.x + 256 * j;
        ((__half2*)dst)[i * 2]     = __floats2half2_rn(v[j].x, v[j].y);
        ((__half2*)dst)[i * 2 + 1] = __floats2half2_rn(v[j].z, v[j].w);
    }
}

// ---------------------------------------------------------------------------
// Warp-specialized fp16 NT GEMM:  C[M,N] = A[M,K]*B[N,K]^T + bias.
// CTA = 160 threads: warps 0-3 consumers (64x64 tiles of a 128x128 CTA tile),
// warp 4 producer (all cp.async). No __syncthreads in the main loop; stage
// hand-off via mbarriers:
//   full[s]:  init 32, armed by cp.async.mbarrier.arrive.NOINC (one per
//             producer lane, fires when that lane's cp.asyncs complete)
//   empty[s]: init 4, armed by one lane of each consumer warp
// 3-stage ring, BK=64, 2 CTAs/SM.
// ---------------------------------------------------------------------------
struct GemmArgs {
    const __half* A;
    const __half* Bm[3];
    const float*  bias[3];
    void*         C[3];
};

#define BM 128
#define BN 128
#define BK 64
#define SST 72                        // smem row stride (halfs)
#define NS 3
#define NKT 16                        // K=1024 / BK
#define STG_ROWS (BM + BN)            // 256: A rows | B rows
#define STAGE_B (STG_ROWS * SST * 2)  // 36864
#define SMEM_BYTES (NS * STAGE_B + 64)

__device__ __forceinline__ void mma16816(float c[4], uint32_t a0, uint32_t a1,
                                         uint32_t a2, uint32_t a3,
                                         uint32_t b0, uint32_t b1) {
    asm volatile(
        "mma.sync.aligned.m16n8k16.row.col.f32.f16.f16.f32 "
        "{%0,%1,%2,%3}, {%4,%5,%6,%7}, {%8,%9}, {%0,%1,%2,%3};\n"
        : "+f"(c[0]), "+f"(c[1]), "+f"(c[2]), "+f"(c[3])
        : "r"(a0), "r"(a1), "r"(a2), "r"(a3), "r"(b0), "r"(b1));
}

__device__ __forceinline__ void ldsm4(uint32_t& r0, uint32_t& r1,
                                      uint32_t& r2, uint32_t& r3, uint32_t a) {
    asm volatile("ldmatrix.sync.aligned.m8n8.x4.shared.b16 {%0,%1,%2,%3}, [%4];"
                 : "=r"(r0), "=r"(r1), "=r"(r2), "=r"(r3) : "r"(a));
}

__device__ __forceinline__ void cp16(uint32_t s, const void* g) {
    asm volatile("cp.async.cg.shared.global [%0], [%1], 16;" :: "r"(s), "l"(g));
}

__device__ __forceinline__ void mbar_init(uint32_t a, uint32_t cnt) {
    asm volatile("mbarrier.init.shared.b64 [%0], %1;" :: "r"(a), "r"(cnt) : "memory");
}
__device__ __forceinline__ void mbar_arrive(uint32_t a) {
    asm volatile("mbarrier.arrive.shared.b64 _, [%0];" :: "r"(a) : "memory");
}
__device__ __forceinline__ void cpasync_mbar_arrive_noinc(uint32_t a) {
    asm volatile("cp.async.mbarrier.arrive.noinc.shared.b64 [%0];" :: "r"(a) : "memory");
}
__device__ __forceinline__ void mbar_wait(uint32_t mbar, int parity) {
    asm volatile(
        "{\n\t.reg .pred P1;\n\t"
        "WAIT_LOOP_%=:\n\t"
        "mbarrier.try_wait.parity.shared.b64 P1, [%0], %1, 0x989680;\n\t"
        "@P1 bra.uni WAIT_DONE_%=;\n\t"
        "bra.uni WAIT_LOOP_%=;\n\t"
        "WAIT_DONE_%=:\n\t}"
        :: "r"(mbar), "r"(parity) : "memory");
}

template <bool HALF_OUT>
__global__ void __launch_bounds__(160, 2) gemm_kernel(GemmArgs args) {
    extern __shared__ __half smem[];

    const int z = blockIdx.z;
    const __half* __restrict__ A   = args.A;
    const __half* __restrict__ Bw  = args.Bm[z];
    const float* __restrict__ bias = args.bias[z];

    const int bn  = blockIdx.x * BN;
    const int bm  = blockIdx.y * BM;
    const int tid = threadIdx.x;
    const int warp = tid >> 5, lane = tid & 31;

    const uint32_t sbase = (uint32_t)__cvta_generic_to_shared(smem);
    const uint32_t mb    = sbase + NS * STAGE_B;         // barrier block
    auto fullb  = [&](int s) -> uint32_t { return mb + 8 * s; };
    auto emptyb = [&](int s) -> uint32_t { return mb + 24 + 8 * s; };
    auto srow = [&](int s, int r, int c) -> uint32_t {
        return sbase + (uint32_t)(((s * STG_ROWS + r) * SST + c) * 2);
    };

    if (tid == 0) {
#pragma unroll
        for (int s = 0; s < NS; s++) {
            mbar_init(fullb(s), 32);   // producer lanes (cp.async completion)
            mbar_init(emptyb(s), 4);   // consumer warps
        }
    }
    __syncthreads();

    if (warp == 4) {
        // ------------------------- producer -------------------------
        for (int kt = 0; kt < NKT; kt++) {
            const int s = kt % NS;
            if (kt >= NS) mbar_wait(emptyb(s), ((kt / NS) - 1) & 1);
            const int kc = kt * BK;
#pragma unroll 8
            for (int j = 0; j < 64; j++) {
                const int c   = lane + 32 * j;        // 0..2047 16B-chunks
                const int row = c >> 3;               // 8 chunks per 64-half row
                const int c8  = (c & 7) * 8;
                const __half* g = (row < BM)
                    ? A  + (size_t)(bm + row) * DD + kc + c8
                    : Bw + (size_t)(bn + row - BM) * DD + kc + c8;
                cp16(srow(s, row, c8), g);
            }
            cpasync_mbar_arrive_noinc(fullb(s));
        }
        return;
    }

    // --------------------------- consumers ---------------------------
    const int wm = (warp >> 1) * 64;   // 0/64
    const int wn = (warp & 1) * 64;    // 0/64

    const int alr = lane & 15, alc = (lane >> 4) * 8;     // A x4 (16 rows)
    const int blr = ((lane >> 4) & 1) * 8 + (lane & 7);   // B x4
    const int blc = ((lane >> 3) & 1) * 8;

    float acc[4][8][4];
#pragma unroll
    for (int i = 0; i < 4; i++)
#pragma unroll
        for (int j = 0; j < 8; j++)
#pragma unroll
            for (int r = 0; r < 4; r++) acc[i][j][r] = 0.f;

    for (int kt = 0; kt < NKT; kt++) {
        const int s = kt % NS;
        mbar_wait(fullb(s), (kt / NS) & 1);
#pragma unroll
        for (int kk = 0; kk < 4; kk++) {
            const int k0 = kk * 16;
            uint32_t a[4][4], b[8][2];
#pragma unroll
            for (int i = 0; i < 4; i++)
                ldsm4(a[i][0], a[i][1], a[i][2], a[i][3],
                      srow(s, wm + i * 16 + alr, k0 + alc));
#pragma unroll
            for (int jp = 0; jp < 4; jp++)
                ldsm4(b[2 * jp][0], b[2 * jp][1],
                      b[2 * jp + 1][0], b[2 * jp + 1][1],
                      srow(s, BM + wn + jp * 16 + blr, k0 + blc));
#pragma unroll
            for (int i = 0; i < 4; i++)
#pragma unroll
                for (int j = 0; j < 8; j++)
                    mma16816(acc[i][j], a[i][0], a[i][1], a[i][2], a[i][3],
                             b[j][0], b[j][1]);
        }
        if (lane == 0) mbar_arrive(emptyb(s));
    }

    // epilogue: bias + store (fp16 or fp32)
    const int qr = lane >> 2, qc = lane & 3;
#pragma unroll
    for (int i = 0; i < 4; i++) {
#pragma unroll
        for (int j = 0; j < 8; j++) {
            const int row = bm + wm + i * 16 + qr;
            const int col = bn + wn + j * 8 + qc * 2;
            const float b0 = bias[col], b1 = bias[col + 1];
            const float v00 = acc[i][j][0] + b0, v01 = acc[i][j][1] + b1;
            const float v10 = acc[i][j][2] + b0, v11 = acc[i][j][3] + b1;
            if (HALF_OUT) {
                __half* C = (__half*)args.C[z];
                *(__half2*)&C[(size_t)row * DD + col]       = __floats2half2_rn(v00, v01);
                *(__half2*)&C[(size_t)(row + 8) * DD + col] = __floats2half2_rn(v10, v11);
            } else {
                float* C = (float*)args.C[z];
                *(float2*)&C[(size_t)row * DD + col]       = make_float2(v00, v01);
                *(float2*)&C[(size_t)(row + 8) * DD + col] = make_float2(v10, v11);
            }
        }
    }
}

// ---------------------------------------------------------------------------
// Per-token attention over the HEAD axis. One warp per token; fp16 in/out,
// fp32 compute.
// ---------------------------------------------------------------------------
__global__ void __launch_bounds__(64) attn_kernel(
    const __half* __restrict__ Q, const __half* __restrict__ K,
    const __half* __restrict__ V, __half* __restrict__ Ch) {
    __shared__ float sQ[2][DD], sK[2][DD], sV[2][DD];
    __shared__ float sS[2][HH][HH];

    const int warp = threadIdx.x >> 5, lane = threadIdx.x & 31;
    const size_t t = (size_t)blockIdx.x * 2 + warp;

    const __half2* q2 = (const __half2*)(Q + t * DD);
    const __half2* k2 = (const __half2*)(K + t * DD);
    const __half2* v2 = (const __half2*)(V + t * DD);
#pragma unroll
    for (int i = lane; i < DD / 2; i += 32) {
        ((float2*)sQ[warp])[i] = __half22float2(q2[i]);
        ((float2*)sK[warp])[i] = __half22float2(k2[i]);
        ((float2*)sV[warp])[i] = __half22float2(v2[i]);
    }
    __syncwarp();

    for (int p = lane; p < HH * HH; p += 32) {
        const int h = p >> 4, g = p & 15;
        const float* q = &sQ[warp][h * DHH];
        const float* k = &sK[warp][g * DHH];
        float s = 0.f;
#pragma unroll
        for (int d = 0; d < DHH; d++) s += q[d] * k[d];
        sS[warp][h][g] = s * 0.125f;   // 1/sqrt(64)
    }
    __syncwarp();

    if (lane < HH) {
        float mx = -1e30f;
#pragma unroll
        for (int g = 0; g < HH; g++) mx = fmaxf(mx, sS[warp][lane][g]);
        float sum = 0.f;
#pragma unroll
        for (int g = 0; g < HH; g++) {
            float e = expf(sS[warp][lane][g] - mx);
            sS[warp][lane][g] = e;
            sum += e;
        }
        const float inv = 1.f / sum;
#pragma unroll
        for (int g = 0; g < HH; g++) sS[warp][lane][g] *= inv;
    }
    __syncwarp();

    __half* out = Ch + t * DD;
    for (int o2 = lane; o2 < DD / 2; o2 += 32) {
        const int o = o2 * 2;
        const int h = o >> 6, d = o & 63;
        float c0 = 0.f, c1 = 0.f;
#pragma unroll
        for (int g = 0; g < HH; g++) {
            c0 += sS[warp][h][g] * sV[warp][g * DHH + d];
            c1 += sS[warp][h][g] * sV[warp][g * DHH + d + 1];
        }
        ((__half2*)out)[o2] = __floats2half2_rn(c0, c1);
    }
}

// ---------------------------------------------------------------------------
// Launch
// ---------------------------------------------------------------------------
extern "C" void kernel_launch(void* const* d_in, const int* in_sizes, int n_in,
                              void* d_out, int out_size) {
    (void)in_sizes; (void)n_in; (void)out_size;
    const float* x  = (const float*)d_in[0];
    const float* wq = (const float*)d_in[1];
    const float* bq = (const float*)d_in[2];
    const float* wk = (const float*)d_in[3];
    const float* bk = (const float*)d_in[4];
    const float* wv = (const float*)d_in[5];
    const float* bv = (const float*)d_in[6];
    const float* wo = (const float*)d_in[7];
    const float* bo = (const float*)d_in[8];
    float* out = (float*)d_out;

    __half *Xh, *Wh, *Qh, *Kh, *Vh, *Ch;
    cudaGetSymbolAddress((void**)&Xh, g_Xh);
    cudaGetSymbolAddress((void**)&Wh, g_Wh);
    cudaGetSymbolAddress((void**)&Qh, g_Qh);
    cudaGetSymbolAddress((void**)&Kh, g_Kh);
    cudaGetSymbolAddress((void**)&Vh, g_Vh);
    cudaGetSymbolAddress((void**)&Ch, g_Ch);
    const size_t WS = (size_t)DD * DD;

    cudaFuncSetAttribute(gemm_kernel<true>,
                         cudaFuncAttributeMaxDynamicSharedMemorySize, SMEM_BYTES);
    cudaFuncSetAttribute(gemm_kernel<false>,
                         cudaFuncAttributeMaxDynamicSharedMemorySize, SMEM_BYTES);

    // 1) fused converts to fp16 (x + 4 weights in one launch, MLP=4)
    CvtArgs ca;
    ca.x = x; ca.w[0] = wq; ca.w[1] = wk; ca.w[2] = wv; ca.w[3] = wo;
    ca.xh = Xh; ca.wh = Wh;
    cvt_kernel<<<XBLKS + 4 * WBLKS, 256>>>(ca);

    // 2) fused QKV GEMMs (z = q/k/v) -> fp16 outputs
    GemmArgs ga;
    ga.A = Xh;
    ga.Bm[0] = Wh + 0 * WS; ga.Bm[1] = Wh + 1 * WS; ga.Bm[2] = Wh + 2 * WS;
    ga.bias[0] = bq; ga.bias[1] = bk; ga.bias[2] = bv;
    ga.C[0] = Qh; ga.C[1] = Kh; ga.C[2] = Vh;
    gemm_kernel<true><<<dim3(DD / BN, TT / BM, 3), 160, SMEM_BYTES>>>(ga);

    // 3) per-token head-axis attention (fp16 in/out)
    attn_kernel<<<TT / 2, 64>>>(Qh, Kh, Vh, Ch);

    // 4) output projection -> fp32 d_out
    GemmArgs go;
    go.A = Ch;
    go.Bm[0] = Wh + 3 * WS; go.Bm[1] = go.Bm[0]; go.Bm[2] = go.Bm[0];
    go.bias[0] = bo; go.bias[1] = bo; go.bias[2] = bo;
    go.C[0] = out; go.C[1] = out; go.C[2] = out;
    gemm_kernel<false><<<dim3(DD / BN, TT / BM, 1), 160, SMEM_BYTES>>>(go);
}